// round 1
// baseline (speedup 1.0000x reference)
#include <cuda_runtime.h>
#include <cuda_bf16.h>
#include <mma.h>
#include <math.h>
#include <stdint.h>

using namespace nvcuda;

// Problem constants
#define NTOK   16384      // B*S
#define DMODEL 1024
#define NHEAD  16
#define HD     64         // head dim
#define NP     32         // experts per head
#define NR     8          // slots per expert
#define NPR    256        // NP*NR

// 64 MB scratch for heads (intermediate), allocation-free per harness rules
__device__ float g_heads[(size_t)NTOK * DMODEL];

// ---------------------------------------------------------------------------
// Warp reduction helpers
// ---------------------------------------------------------------------------
__device__ __forceinline__ float warp_max(float v) {
#pragma unroll
    for (int o = 16; o > 0; o >>= 1) v = fmaxf(v, __shfl_xor_sync(0xffffffffu, v, o));
    return v;
}
__device__ __forceinline__ float warp_sum(float v) {
#pragma unroll
    for (int o = 16; o > 0; o >>= 1) v += __shfl_xor_sync(0xffffffffu, v, o);
    return v;
}
__device__ __forceinline__ float g8_max(float v) {
#pragma unroll
    for (int o = 4; o > 0; o >>= 1) v = fmaxf(v, __shfl_xor_sync(0xffffffffu, v, o));
    return v;
}
__device__ __forceinline__ float g8_sum(float v) {
#pragma unroll
    for (int o = 4; o > 0; o >>= 1) v += __shfl_xor_sync(0xffffffffu, v, o);
    return v;
}

// ---------------------------------------------------------------------------
// Attention kernel: one block = (head h, chunk of 512 tokens), 16 warps.
// Each warp handles one token per pass (32 passes). SMEM holds the full
// per-head K/V/W_router state.
//
// SMEM layouts (conflict-free for the access patterns used):
//   Wr_s[d][p]        : logits — lane=p reads consecutive banks, x[d] broadcast
//   Ks  [d][p*8+r]    : scores — lane=(e,r), address p*8+r, <=4-way worst case
//   Vs  [p*8+r][d]    : combine — lane=d consecutive, row broadcast
// ---------------------------------------------------------------------------
#define ATTN_THREADS 512
#define ATTN_WARPS   16
#define TOK_PER_BLK  512
#define ATTN_SMEM_FLOATS (2048 + 16384 + 16384 + ATTN_WARPS * 64)

__global__ __launch_bounds__(ATTN_THREADS) void attn_kernel(
    const float* __restrict__ x,
    const float* __restrict__ Kst,
    const float* __restrict__ Vst,
    const float* __restrict__ Wrt)
{
    extern __shared__ float sm[];
    float* Wr_s = sm;                 // [64][32]   = 2048
    float* Ks   = sm + 2048;          // [64][256]  = 16384
    float* Vs   = Ks + 16384;         // [256][64]  = 16384
    float* xs   = Vs + 16384;         // [16][64]

    const int h    = blockIdx.x;
    const int tid  = threadIdx.x;
    const int wid  = tid >> 5;
    const int lane = tid & 31;
    const unsigned FULL = 0xffffffffu;

    // Stage per-head weights into SMEM
    for (int i = tid; i < HD * NP; i += ATTN_THREADS)
        Wr_s[i] = Wrt[h * HD * NP + i];                      // [d][p] direct copy
    const float* Kh = Kst + (size_t)h * NPR * HD;
    for (int i = tid; i < NPR * HD; i += ATTN_THREADS) {
        int d = i & 63, pr = i >> 6;
        Ks[d * NPR + pr] = Kh[i];                            // transpose to [d][pr]
    }
    const float* Vh = Vst + (size_t)h * NPR * HD;
    for (int i = tid; i < NPR * HD; i += ATTN_THREADS)
        Vs[i] = Vh[i];                                       // [pr][d] direct copy
    __syncthreads();

    float* xw = xs + wid * 64;
    const int e8 = lane >> 3;          // which of the 4 selected experts
    const int r8 = lane & 7;           // slot within expert

    for (int it = 0; it < TOK_PER_BLK / ATTN_WARPS; ++it) {
        const int tk = blockIdx.y * TOK_PER_BLK + it * ATTN_WARPS + wid;
        const float* xp = x + (size_t)tk * DMODEL + h * HD;

        // load this token's head slice into SMEM (float2 per lane)
        float2 xv = ((const float2*)xp)[lane];
        xw[2 * lane]     = xv.x;
        xw[2 * lane + 1] = xv.y;
        __syncwarp();

        // ---- router logits: lane = expert p ----
        float lg = 0.f;
#pragma unroll
        for (int d = 0; d < HD; ++d)
            lg = fmaf(xw[d], Wr_s[d * NP + lane], lg);

        // ---- top-4 threshold: remove max 3 times, 4th max is the threshold
        float m0  = warp_max(lg);
        float cur = lg, mm = m0;
#pragma unroll
        for (int i = 0; i < 3; ++i) {
            cur = (cur == mm) ? -INFINITY : cur;
            mm  = warp_max(cur);
        }
        const bool sel = (lg >= mm);
        float ev   = sel ? __expf(lg - m0) : 0.f;
        float gate = ev / warp_sum(ev);

        // extract the 4 selected expert indices + their gates (uniform lanes)
        unsigned bal = __ballot_sync(FULL, sel);
        int pa0, pa1, pa2, pa3;
        {
            unsigned b = bal;
            pa0 = __ffs(b) - 1; b &= b - 1;
            pa1 = __ffs(b) - 1; b &= b - 1;
            pa2 = __ffs(b) - 1; b &= b - 1;
            pa3 = __ffs(b) - 1;
            if (pa0 < 0) pa0 = 0;          // degenerate-tie safety
            if (pa1 < 0) pa1 = pa0;
            if (pa2 < 0) pa2 = pa1;
            if (pa3 < 0) pa3 = pa2;
        }
        const float ga0 = __shfl_sync(FULL, gate, pa0);
        const float ga1 = __shfl_sync(FULL, gate, pa1);
        const float ga2 = __shfl_sync(FULL, gate, pa2);
        const float ga3 = __shfl_sync(FULL, gate, pa3);

        const int   p_my = (e8 == 0) ? pa0 : (e8 == 1) ? pa1 : (e8 == 2) ? pa2 : pa3;
        const float g_my = (e8 == 0) ? ga0 : (e8 == 1) ? ga1 : (e8 == 2) ? ga2 : ga3;

        // ---- scores for lane's (expert, slot) ----
        const float* kc = Ks + p_my * NR + r8;
        float sc = 0.f;
#pragma unroll
        for (int d = 0; d < HD; ++d)
            sc = fmaf(xw[d], kc[d * NPR], sc);
        sc *= 0.125f;                               // 1/sqrt(64)

        // softmax over the 8 slots of this expert
        const float sm8 = g8_max(sc);
        const float ex  = __expf(sc - sm8);
        const float wv  = (ex / g8_sum(ex)) * g_my;

        // ---- combine with V: lane = output dim (d and d+32) ----
        float acc0 = 0.f, acc1 = 0.f;
#pragma unroll
        for (int j = 0; j < 32; ++j) {
            const float wj = __shfl_sync(FULL, wv, j);
            const int   pj = (j < 8) ? pa0 : (j < 16) ? pa1 : (j < 24) ? pa2 : pa3;
            const float* vr = Vs + (pj * NR + (j & 7)) * HD;
            acc0 = fmaf(wj, vr[lane], acc0);
            acc1 = fmaf(wj, vr[lane + 32], acc1);
        }

        const size_t o = (size_t)tk * DMODEL + h * HD + lane;
        g_heads[o]      = acc0;
        g_heads[o + 32] = acc1;
        __syncwarp();   // protect xw before next token's store
    }
}

// ---------------------------------------------------------------------------
// Output projection: C[16384,1024] = heads @ W_out + b_out
// WMMA tf32 m16n16k8, block tile 128x64, 8 warps (4x2), warp tile 32x32.
// tf32 rounding keeps rel err ~2e-4 (fp32-grade for the 1e-3 gate).
// ---------------------------------------------------------------------------
#define GM 16384
#define GN 1024
#define GK 1024

__global__ __launch_bounds__(256) void gemm_kernel(
    const float* __restrict__ Bmat,      // W_out [K,N] row-major
    const float* __restrict__ bias,      // [N]
    float* __restrict__ C)               // [M,N] row-major
{
    __shared__ float As[128][16];        // A tile (row-major)
    __shared__ float Bs[16][64];         // B tile (row-major)
    __shared__ float biasT[16][64];

    const float* A = g_heads;
    const int tid = threadIdx.x;
    const int wid = tid >> 5;
    const int wm  = wid >> 1;            // 0..3  (M direction)
    const int wn  = wid & 1;             // 0..1  (N direction)
    const int bm  = blockIdx.y << 7;     // *128
    const int bn  = blockIdx.x << 6;     // *64

    // replicate bias into a 16-row tile so accumulators init from it
    for (int i = tid; i < 16 * 64; i += 256)
        biasT[i >> 6][i & 63] = bias[bn + (i & 63)];
    __syncthreads();

    wmma::fragment<wmma::accumulator, 16, 16, 8, float> cf[2][2];
#pragma unroll
    for (int i = 0; i < 2; ++i)
#pragma unroll
        for (int j = 0; j < 2; ++j)
            wmma::load_matrix_sync(cf[i][j], &biasT[0][wn * 32 + j * 16], 64,
                                   wmma::mem_row_major);

    const int ar = tid >> 2;             // 0..63
    const int ac = (tid & 3) << 2;       // 0,4,8,12
    const int br = tid >> 4;             // 0..15
    const int bc = (tid & 15) << 2;      // 0..60

    for (int kt = 0; kt < GK; kt += 16) {
#pragma unroll
        for (int rr = 0; rr < 2; ++rr) {
            float4 v = *(const float4*)(A + (size_t)(bm + ar + rr * 64) * GK + kt + ac);
            v.x = wmma::__float_to_tf32(v.x);
            v.y = wmma::__float_to_tf32(v.y);
            v.z = wmma::__float_to_tf32(v.z);
            v.w = wmma::__float_to_tf32(v.w);
            *(float4*)&As[ar + rr * 64][ac] = v;
        }
        {
            float4 v = *(const float4*)(Bmat + (size_t)(kt + br) * GN + bn + bc);
            v.x = wmma::__float_to_tf32(v.x);
            v.y = wmma::__float_to_tf32(v.y);
            v.z = wmma::__float_to_tf32(v.z);
            v.w = wmma::__float_to_tf32(v.w);
            *(float4*)&Bs[br][bc] = v;
        }
        __syncthreads();

#pragma unroll
        for (int ks = 0; ks < 16; ks += 8) {
            wmma::fragment<wmma::matrix_a, 16, 16, 8, wmma::precision::tf32,
                           wmma::row_major> af[2];
            wmma::fragment<wmma::matrix_b, 16, 16, 8, wmma::precision::tf32,
                           wmma::row_major> bf[2];
#pragma unroll
            for (int i = 0; i < 2; ++i)
                wmma::load_matrix_sync(af[i], &As[wm * 32 + i * 16][ks], 16);
#pragma unroll
            for (int j = 0; j < 2; ++j)
                wmma::load_matrix_sync(bf[j], &Bs[ks][wn * 32 + j * 16], 64);
#pragma unroll
            for (int i = 0; i < 2; ++i)
#pragma unroll
                for (int j = 0; j < 2; ++j)
                    wmma::mma_sync(cf[i][j], af[i], bf[j], cf[i][j]);
        }
        __syncthreads();
    }

#pragma unroll
    for (int i = 0; i < 2; ++i)
#pragma unroll
        for (int j = 0; j < 2; ++j)
            wmma::store_matrix_sync(
                &C[(size_t)(bm + wm * 32 + i * 16) * GN + bn + wn * 32 + j * 16],
                cf[i][j], GN, wmma::mem_row_major);
}

// ---------------------------------------------------------------------------
extern "C" void kernel_launch(void* const* d_in, const int* in_sizes, int n_in,
                              void* d_out, int out_size)
{
    const float* x    = (const float*)d_in[0];   // [B,S,DM]
    const float* Kst  = (const float*)d_in[1];   // [H,P,R,D]
    const float* Vst  = (const float*)d_in[2];   // [H,P,R,D]
    const float* Wrt  = (const float*)d_in[3];   // [H,D,P]
    const float* Wout = (const float*)d_in[4];   // [DM,DM]
    const float* bout = (const float*)d_in[5];   // [DM]
    float* out = (float*)d_out;                  // [B,S,DM]

    const int attn_smem = ATTN_SMEM_FLOATS * (int)sizeof(float);   // 143,360 B
    cudaFuncSetAttribute(attn_kernel,
                         cudaFuncAttributeMaxDynamicSharedMemorySize, attn_smem);

    attn_kernel<<<dim3(NHEAD, NTOK / TOK_PER_BLK), ATTN_THREADS, attn_smem>>>(
        x, Kst, Vst, Wrt);

    gemm_kernel<<<dim3(GN / 64, GM / 128), 256>>>(Wout, bout, out);
}